// round 1
// baseline (speedup 1.0000x reference)
#include <cuda_runtime.h>
#include <cstdint>

// Problem geometry (fixed for this instance): B=128, N=16384, T=64.
// N is hardcoded; B and T derived from in_sizes/out_size for robustness.
constexpr int N_ELEM   = 16384;
constexpr int NTHREADS = 1024;
constexpr int NWARPS   = 32;          // one CTA = one full row
constexpr int SEGS     = NWARPS * 4;  // 128 segments of 128 elements each

__global__ __launch_bounds__(NTHREADS, 1)
void heat1d_unroll_kernel(const float* __restrict__ f0,
                          const float* __restrict__ log_alpha,
                          float* __restrict__ out, int T)
{
    // Double-buffered segment-boundary halos (first/last element of each
    // 128-element segment). 2 KB total.
    __shared__ float segF[2][SEGS];
    __shared__ float segL[2][SEGS];

    const int b   = blockIdx.x;
    const int tid = threadIdx.x;
    const int w   = tid >> 5;
    const int l   = tid & 31;

    float alpha = expf(*log_alpha);
    alpha = fminf(fmaxf(alpha, 0.001f), 1.0f);

    const float4* rowv = reinterpret_cast<const float4*>(f0 + (size_t)b * N_ELEM);
    float4*       outv = reinterpret_cast<float4*>(out + (size_t)b * T * N_ELEM);

    // Warp w owns elements [512w, 512w+512). Lane l holds float4 j at
    // element offset 128j + 4l -> store instructions are fully coalesced
    // 512B warp transactions, and stencil neighbors are in adjacent lanes.
    const int vbase = w * 128;  // float4 index of this warp's chunk start

    float4 v[4];
#pragma unroll
    for (int j = 0; j < 4; j++) v[j] = rowv[vbase + j * 32 + l];

    // Emit t = 0 (states[0] = x0).
#pragma unroll
    for (int j = 0; j < 4; j++) outv[vbase + j * 32 + l] = v[j];

    if (l == 0) {
#pragma unroll
        for (int j = 0; j < 4; j++) segF[0][w * 4 + j] = v[j].x;
    }
    if (l == 31) {
#pragma unroll
        for (int j = 0; j < 4; j++) segL[0][w * 4 + j] = v[j].w;
    }
    __syncthreads();

    for (int t = 1; t < T; t++) {
        const int p = (t - 1) & 1;  // halo buffer produced last step
        const int q = t & 1;        // halo buffer for this step's result
        float4 nv[4];

#pragma unroll
        for (int j = 0; j < 4; j++) {
            // Left neighbor of my .x = previous lane's .w; right neighbor of
            // my .w = next lane's .x. Boundary lanes patch from smem halos.
            float up = __shfl_up_sync(0xffffffffu, v[j].w, 1);
            float dn = __shfl_down_sync(0xffffffffu, v[j].x, 1);
            const int s = w * 4 + j;
            if (l == 0)  up = (s == 0)        ? v[j].x : segL[p][s - 1];  // edge clamp at n=0
            if (l == 31) dn = (s == SEGS - 1) ? v[j].w : segF[p][s + 1];  // edge clamp at n=N-1

            float lx = (up     + v[j].y) - 2.0f * v[j].x;
            float ly = (v[j].x + v[j].z) - 2.0f * v[j].y;
            float lz = (v[j].y + v[j].w) - 2.0f * v[j].z;
            float lw = (v[j].z + dn    ) - 2.0f * v[j].w;

            nv[j].x = fmaf(alpha, lx, v[j].x);
            nv[j].y = fmaf(alpha, ly, v[j].y);
            nv[j].z = fmaf(alpha, lz, v[j].z);
            nv[j].w = fmaf(alpha, lw, v[j].w);
        }

        // Publish next-step halos before the barrier.
        if (l == 0) {
#pragma unroll
            for (int j = 0; j < 4; j++) segF[q][w * 4 + j] = nv[j].x;
        }
        if (l == 31) {
#pragma unroll
            for (int j = 0; j < 4; j++) segL[q][w * 4 + j] = nv[j].w;
        }

        // Stream state t to GMEM (fire-and-forget STG.128, fully coalesced).
        float4* outt = outv + (size_t)t * (N_ELEM / 4);
#pragma unroll
        for (int j = 0; j < 4; j++) {
            outt[vbase + j * 32 + l] = nv[j];
            v[j] = nv[j];
        }
        __syncthreads();
    }
}

extern "C" void kernel_launch(void* const* d_in, const int* in_sizes, int n_in,
                              void* d_out, int out_size)
{
    const float* f0        = (const float*)d_in[0];
    const float* log_alpha = (const float*)d_in[1];
    float*       out       = (float*)d_out;

    const int B = in_sizes[0] / N_ELEM;   // 128
    const int T = out_size / in_sizes[0]; // 64

    heat1d_unroll_kernel<<<B, NTHREADS>>>(f0, log_alpha, out, T);
}

// round 2
// speedup vs baseline: 1.1733x; 1.1733x over previous
#include <cuda_runtime.h>
#include <cstdint>

// B=128, N=16384, T=64. Each warp independently evolves a 640-element window
// (512 owned + 64-element halo each side, halo >= T-1=63) entirely in
// registers. No barriers, no shared memory, no inter-warp communication.
constexpr int N_ELEM   = 16384;
constexpr int NTHREADS = 256;          // 8 warps per CTA

__global__ __launch_bounds__(NTHREADS)
void heat1d_warp_kernel(const float* __restrict__ f0,
                        const float* __restrict__ log_alpha,
                        float* __restrict__ out, int T)
{
    const int tid = threadIdx.x;
    const int l   = tid & 31;
    const int gw  = blockIdx.x * (NTHREADS / 32) + (tid >> 5);
    const int b   = gw >> 5;   // row index      (32 warps per row)
    const int w   = gw & 31;   // warp-in-row

    float alpha = expf(*log_alpha);
    alpha = fminf(fmaxf(alpha, 0.001f), 1.0f);

    // Window: 640 elements = 160 float4. Interleaved layout: lane l holds
    // float4 index j*32+l (window elements [128j+4l, 128j+4l+4)).
    const int wstart = w * 512;
    int lbase = wstart - 64;
    if (lbase < 0) lbase = 0;
    if (lbase > N_ELEM - 640) lbase = N_ELEM - 640;
    const int s4 = (wstart - lbase) >> 2;   // store-range start in float4s: 0, 16, or 32

    const float4* inv = reinterpret_cast<const float4*>(f0 + (size_t)b * N_ELEM)
                        + (lbase >> 2);
    float4* outrow    = reinterpret_cast<float4*>(out + (size_t)b * T * N_ELEM)
                        + (lbase >> 2);

    float4 v[5];
#pragma unroll
    for (int j = 0; j < 5; j++) v[j] = inv[j * 32 + l];

    // Emit t = 0 (only the warp's owned 512 elements = float4s [s4, s4+128)).
#pragma unroll
    for (int j = 0; j < 5; j++) {
        const int f = j * 32 + l;
        if (f >= s4 && f < s4 + 128) outrow[f] = v[j];
    }

    const int upsrc = (l + 31) & 31;   // rotated shuffle sources
    const int dnsrc = (l + 1)  & 31;

    for (int t = 1; t < T; t++) {
        // Neighbor exchange: rotated shuffles with per-lane source selection.
        // Dest lane 0 of the "up" shuffle reads src lane 31, which supplies the
        // previous float4's .w (crossing the j boundary in one shuffle).
        float up[5], dn[5];
#pragma unroll
        for (int j = 0; j < 5; j++) {
            float us = (l == 31 && j > 0) ? v[j - 1].w : v[j].w;
            float ds = (l == 0  && j < 4) ? v[j + 1].x : v[j].x;
            up[j] = __shfl_sync(0xffffffffu, us, upsrc);
            dn[j] = __shfl_sync(0xffffffffu, ds, dnsrc);
        }
        // Window-edge clamp. At true row ends the window is flush with the row,
        // so this is exactly the reference's edge padding; at interior fake
        // edges the resulting staleness never reaches the stored region.
        if (l == 0)  up[0] = v[0].x;
        if (l == 31) dn[4] = v[4].w;

        float4* outt = outrow + (size_t)t * (N_ELEM / 4);
#pragma unroll
        for (int j = 0; j < 5; j++) {
            const float lx = (up[j]  + v[j].y) - 2.0f * v[j].x;
            const float ly = (v[j].x + v[j].z) - 2.0f * v[j].y;
            const float lz = (v[j].y + v[j].w) - 2.0f * v[j].z;
            const float lw = (v[j].z + dn[j] ) - 2.0f * v[j].w;
            v[j].x = fmaf(alpha, lx, v[j].x);
            v[j].y = fmaf(alpha, ly, v[j].y);
            v[j].z = fmaf(alpha, lz, v[j].z);
            v[j].w = fmaf(alpha, lw, v[j].w);

            const int f = j * 32 + l;
            if (f >= s4 && f < s4 + 128) outt[f] = v[j];
        }
    }
}

extern "C" void kernel_launch(void* const* d_in, const int* in_sizes, int n_in,
                              void* d_out, int out_size)
{
    const float* f0        = (const float*)d_in[0];
    const float* log_alpha = (const float*)d_in[1];
    float*       out       = (float*)d_out;

    const int B = in_sizes[0] / N_ELEM;    // 128
    const int T = out_size / in_sizes[0];  // 64

    const int total_warps = B * 32;        // 32 warps per row
    const int n_blocks    = total_warps / (NTHREADS / 32);  // 512

    heat1d_warp_kernel<<<n_blocks, NTHREADS>>>(f0, log_alpha, out, T);
}

// round 3
// speedup vs baseline: 1.2343x; 1.0519x over previous
#include <cuda_runtime.h>
#include <cstdint>

// B=128, N=16384, T=64. Each warp independently evolves a 384-element window
// (256 owned + 64-elem halo each side, halo >= T-1=63) entirely in registers.
// No barriers, no smem, no inter-warp communication. 64 warps per row,
// 8192 warps total -> ~55 warps/SM for latency hiding.
constexpr int N_ELEM    = 16384;
constexpr int NTHREADS  = 256;     // 8 warps per CTA
constexpr int OWNED     = 256;     // elements owned per warp
constexpr int WIN       = 384;     // window elements (3 float4 per thread)
constexpr int NJ        = 3;       // float4 slots per thread

__global__ __launch_bounds__(NTHREADS)
void heat1d_warp_kernel(const float* __restrict__ f0,
                        const float* __restrict__ log_alpha,
                        float* __restrict__ out, int T)
{
    const int tid = threadIdx.x;
    const int l   = tid & 31;
    const int gw  = blockIdx.x * (NTHREADS / 32) + (tid >> 5);
    const int wpr = N_ELEM / OWNED;       // warps per row = 64
    const int b   = gw / wpr;             // row index
    const int w   = gw % wpr;             // warp-in-row

    float alpha = expf(*log_alpha);
    alpha = fminf(fmaxf(alpha, 0.001f), 1.0f);

    // Window: 384 elements = 96 float4. Interleaved: lane l holds float4
    // j*32+l (window elements [128j+4l, 128j+4l+4)) -> coalesced 512B stores.
    const int wstart = w * OWNED;
    int lbase = wstart - 64;
    if (lbase < 0) lbase = 0;
    if (lbase > N_ELEM - WIN) lbase = N_ELEM - WIN;
    const int s4  = (wstart - lbase) >> 2;    // owned range start in float4s: 0, 16, or 32
    const int e4  = s4 + OWNED / 4;           // owned range end

    const float4* inv = reinterpret_cast<const float4*>(f0 + (size_t)b * N_ELEM)
                        + (lbase >> 2);
    float4* outrow    = reinterpret_cast<float4*>(out + (size_t)b * T * N_ELEM)
                        + (lbase >> 2);

    float4 v[NJ];
#pragma unroll
    for (int j = 0; j < NJ; j++) v[j] = inv[j * 32 + l];

    // Emit t = 0 (only the owned float4 range [s4, e4)).
#pragma unroll
    for (int j = 0; j < NJ; j++) {
        const int f = j * 32 + l;
        if (f >= s4 && f < e4) __stcs(&outrow[f], v[j]);
    }

    const int upsrc = (l + 31) & 31;   // rotated shuffle sources
    const int dnsrc = (l + 1)  & 31;

    float4* outt = outrow;
    for (int t = 1; t < T; t++) {
        outt += N_ELEM / 4;

        // Neighbor exchange: one rotated shuffle per direction per slot.
        // Lane 31's "up" payload for dest lane 0 crosses the j boundary.
        float up[NJ], dn[NJ];
#pragma unroll
        for (int j = 0; j < NJ; j++) {
            float us = (l == 31 && j > 0)      ? v[j - 1].w : v[j].w;
            float ds = (l == 0  && j < NJ - 1) ? v[j + 1].x : v[j].x;
            up[j] = __shfl_sync(0xffffffffu, us, upsrc);
            dn[j] = __shfl_sync(0xffffffffu, ds, dnsrc);
        }
        // Window-edge clamp: at true row ends the window is flush with the
        // row, so this reproduces the reference's edge padding exactly; at
        // interior fake edges the staleness never reaches the owned region.
        if (l == 0)  up[0]      = v[0].x;
        if (l == 31) dn[NJ - 1] = v[NJ - 1].w;

#pragma unroll
        for (int j = 0; j < NJ; j++) {
            const float lx = (up[j]  + v[j].y) - 2.0f * v[j].x;
            const float ly = (v[j].x + v[j].z) - 2.0f * v[j].y;
            const float lz = (v[j].y + v[j].w) - 2.0f * v[j].z;
            const float lw = (v[j].z + dn[j] ) - 2.0f * v[j].w;
            v[j].x = fmaf(alpha, lx, v[j].x);
            v[j].y = fmaf(alpha, ly, v[j].y);
            v[j].z = fmaf(alpha, lz, v[j].z);
            v[j].w = fmaf(alpha, lw, v[j].w);

            const int f = j * 32 + l;
            if (f >= s4 && f < e4) __stcs(&outt[f], v[j]);
        }
    }
}

extern "C" void kernel_launch(void* const* d_in, const int* in_sizes, int n_in,
                              void* d_out, int out_size)
{
    const float* f0        = (const float*)d_in[0];
    const float* log_alpha = (const float*)d_in[1];
    float*       out       = (float*)d_out;

    const int B = in_sizes[0] / N_ELEM;    // 128
    const int T = out_size / in_sizes[0];  // 64

    const int total_warps = B * (N_ELEM / OWNED);           // 8192
    const int n_blocks    = total_warps / (NTHREADS / 32);  // 1024

    heat1d_warp_kernel<<<n_blocks, NTHREADS>>>(f0, log_alpha, out, T);
}